// round 12
// baseline (speedup 1.0000x reference)
#include <cuda_runtime.h>
#include <cuda_fp16.h>
#include <cstdint>
#include <math.h>

// Problem constants
#define BATCH 8
#define SEQ   4096
#define VDIM  1024
#define KQDIM 256

// ---------------------------------------------------------------------------
// Scratch (device globals; no runtime allocation allowed) — all fp16 path
// ---------------------------------------------------------------------------
__device__ half g_in_f16[(size_t)BATCH * SEQ * VDIM];
__device__ half g_wq_f16[(size_t)VDIM * KQDIM];
__device__ half g_wk_f16[(size_t)VDIM * KQDIM];
__device__ half g_wv_f16[(size_t)VDIM * VDIM];
__device__ half g_qT[(size_t)VDIM * BATCH * SEQ];      // [1024 w][32768 n]
__device__ half g_kT[(size_t)VDIM * BATCH * SEQ];
__device__ half g_v_f16[(size_t)BATCH * SEQ * VDIM];   // [32768 n][1024 v]
__device__ half g_att_f16[(size_t)BATCH * VDIM * VDIM]; // logits then weights

// ---------------------------------------------------------------------------
// Helpers
// ---------------------------------------------------------------------------
__device__ __forceinline__ uint32_t smem_to_u32(const void* p) {
    uint32_t a;
    asm("{ .reg .u64 t; cvta.to.shared.u64 t, %1; cvt.u32.u64 %0, t; }"
        : "=r"(a) : "l"(p));
    return a;
}

__device__ __forceinline__ void ldsm_x4(uint32_t addr, uint32_t* r) {
    asm volatile("ldmatrix.sync.aligned.m8n8.x4.shared.b16 {%0,%1,%2,%3}, [%4];"
        : "=r"(r[0]), "=r"(r[1]), "=r"(r[2]), "=r"(r[3]) : "r"(addr));
}

__device__ __forceinline__ void mma_fp16(float* d, const uint32_t* a, const uint32_t* b) {
    asm volatile(
        "mma.sync.aligned.m16n8k16.row.col.f32.f16.f16.f32 "
        "{%0,%1,%2,%3}, {%4,%5,%6,%7}, {%8,%9}, {%0,%1,%2,%3};"
        : "+f"(d[0]), "+f"(d[1]), "+f"(d[2]), "+f"(d[3])
        : "r"(a[0]), "r"(a[1]), "r"(a[2]), "r"(a[3]), "r"(b[0]), "r"(b[1]));
}

#define CP_ASYNC16(s, g) \
    asm volatile("cp.async.cg.shared.global [%0], [%1], 16;" :: "r"(s), "l"(g))
#define CP_COMMIT() asm volatile("cp.async.commit_group;" ::: "memory")
#define CP_WAIT(n)  asm volatile("cp.async.wait_group %0;" :: "n"(n) : "memory")

// SMEM tile geometry: K-chunk 64 halfwords = 128B data + 16B pad = 144B rows.
#define ROWB 144
#define A_COMP (128 * ROWB)            // 18432 (128-row M tile)
#define B_COMP (128 * ROWB)            // 18432
#define STAGE_F16 (A_COMP + B_COMP)    // 36864
#define PIPE_F16 3
#define SMEM_F16 (PIPE_F16 * STAGE_F16)  // 110592 -> 2 CTAs/SM

// ---------------------------------------------------------------------------
// Unified fp16 NT GEMM: C = A * B^T, K-major fp16 operands.
// CTA tile 128x128, K-chunk 64, 3-stage cp.async, 256 threads, 8 warps
// (2x4), warp tile 64x32, fp32 accumulate, 2 CTAs/SM.
// Fragment double-buffering across the 4 kk steps hides ldsm latency.
// EPI: 0 = fp16 store (attn logits)
//      1 = +bias[row] -> fp16; z selects {A,bias,Ch} vs {A2,bias2,Ch2} (q/k)
//      2 = +bias[col] -> fp16 (v projection)
//      3 = gamma*acc + resid -> fp32 (final output)
// ---------------------------------------------------------------------------
template <int EPI>
__global__ __launch_bounds__(256, 2) void gemm_f16(
    const half* __restrict__ A, long long lda, long long a_bs,
    const half* __restrict__ B, long long ldb, long long b_bs,
    float* __restrict__ Cf, half* __restrict__ Ch, long long ldc, long long c_bs,
    const float* __restrict__ bias,
    const float* __restrict__ resid,
    const float* __restrict__ gamma,
    const half* __restrict__ A2,
    const float* __restrict__ bias2,
    half* __restrict__ Ch2,
    int nchunks)
{
    extern __shared__ char smem[];
    const int tid = threadIdx.x;
    const int wid = tid >> 5;
    const int lane = tid & 31;

    const size_t m0 = (size_t)blockIdx.y * 128;
    const size_t n0 = (size_t)blockIdx.x * 128;
    const size_t z = blockIdx.z;
    if (EPI == 1) {
        if (z == 1) { A = A2; bias = bias2; Ch = Ch2; }
    } else {
        A += z * a_bs;
        B += z * b_bs;
    }

    // cp.async mapping: seg = tid&7 (16B of the 128B row), r = tid>>3 (0..31)
    const int seg = tid & 7;
    const int r = tid >> 3;
    const uint32_t sb = smem_to_u32(smem);

    const half* Ag[4];
    uint32_t Asm[4];
#pragma unroll
    for (int j = 0; j < 4; j++) {
        Ag[j] = A + (m0 + r + 32 * j) * (size_t)lda + seg * 8;
        Asm[j] = (r + 32 * j) * ROWB + seg * 16;
    }
    const half* Bg[4];
    uint32_t Bsm[4];
#pragma unroll
    for (int j = 0; j < 4; j++) {
        Bg[j] = B + (n0 + r + 32 * j) * (size_t)ldb + seg * 8;
        Bsm[j] = A_COMP + (r + 32 * j) * ROWB + seg * 16;
    }

    auto load_stage = [&](int kc, int s) {
        const uint32_t st = sb + s * STAGE_F16;
        const size_t ko = (size_t)kc * 64;
#pragma unroll
        for (int j = 0; j < 4; j++) CP_ASYNC16(st + Asm[j], Ag[j] + ko);
#pragma unroll
        for (int j = 0; j < 4; j++) CP_ASYNC16(st + Bsm[j], Bg[j] + ko);
        CP_COMMIT();
    };

    // Warp tile origin (8 warps: 2 x 4)
    const int wm = (wid >> 2) * 64;
    const int wn = (wid & 3) * 32;

    float acc[4][4][4];
#pragma unroll
    for (int i = 0; i < 4; i++)
#pragma unroll
        for (int j = 0; j < 4; j++)
#pragma unroll
            for (int k = 0; k < 4; k++) acc[i][j][k] = 0.f;

    const uint32_t lrow16 = lane & 15;
    const uint32_t lcol16 = (lane >> 4) * 16;
    const uint32_t a_fo = (wm + lrow16) * ROWB + lcol16;           // frag A base
    const uint32_t b_fo = A_COMP + (wn + lrow16) * ROWB + lcol16;  // frag B base

    // Fragment loader for one kk slice
    auto load_frag = [&](uint32_t st, int kk, uint32_t Af[4][4], uint32_t Bf[4][2]) {
        const uint32_t kb = kk * 32;
#pragma unroll
        for (int p = 0; p < 2; p++) {
            uint32_t t[4];
            ldsm_x4(st + b_fo + p * 16 * ROWB + kb, t);
            Bf[2 * p][0] = t[0]; Bf[2 * p][1] = t[2];
            Bf[2 * p + 1][0] = t[1]; Bf[2 * p + 1][1] = t[3];
        }
#pragma unroll
        for (int mt = 0; mt < 4; mt++)
            ldsm_x4(st + a_fo + mt * 16 * ROWB + kb, Af[mt]);
    };

#pragma unroll
    for (int s = 0; s < PIPE_F16 - 1; s++) load_stage(s, s);

    uint32_t Af[2][4][4], Bf[2][4][2];
    for (int i = 0; i < nchunks; i++) {
        CP_WAIT(PIPE_F16 - 2);
        __syncthreads();

        if (i + PIPE_F16 - 1 < nchunks)
            load_stage(i + PIPE_F16 - 1, (i + PIPE_F16 - 1) % PIPE_F16);

        const uint32_t st = sb + (i % PIPE_F16) * STAGE_F16;
        load_frag(st, 0, Af[0], Bf[0]);
#pragma unroll
        for (int kk = 0; kk < 4; kk++) {
            const int cur = kk & 1;
            if (kk < 3) load_frag(st, kk + 1, Af[cur ^ 1], Bf[cur ^ 1]);
#pragma unroll
            for (int mt = 0; mt < 4; mt++)
#pragma unroll
                for (int nt = 0; nt < 4; nt++)
                    mma_fp16(acc[mt][nt], Af[cur][mt], Bf[cur][nt]);
        }
    }

    // Epilogue
    const int er = lane >> 2;
    const int ec = (lane & 3) * 2;
    const float g = (EPI == 3) ? __ldg(gamma) : 0.f;
    const float* rz = (EPI == 3) ? (resid + z * c_bs) : (const float*)nullptr;
    float* Cfz = (EPI == 3) ? (Cf + z * c_bs) : nullptr;
    half* Chz = (EPI == 1) ? Ch : ((EPI == 0 || EPI == 2) ? (Ch + z * c_bs) : nullptr);
#pragma unroll
    for (int mt = 0; mt < 4; mt++) {
#pragma unroll
        for (int half_i = 0; half_i < 2; half_i++) {
            const size_t row = m0 + wm + mt * 16 + er + half_i * 8;
            float rowbias = 0.f;
            if (EPI == 1) rowbias = bias[row];
#pragma unroll
            for (int nt = 0; nt < 4; nt++) {
                const size_t col = n0 + wn + nt * 8 + ec;
                float vx = acc[mt][nt][half_i * 2 + 0];
                float vy = acc[mt][nt][half_i * 2 + 1];
                if (EPI == 1) {
                    vx += rowbias; vy += rowbias;
                    *(__half2*)(Chz + row * (size_t)ldc + col) =
                        __floats2half2_rn(vx, vy);
                } else if (EPI == 2) {
                    vx += bias[col]; vy += bias[col + 1];
                    *(__half2*)(Chz + row * (size_t)ldc + col) =
                        __floats2half2_rn(vx, vy);
                } else if (EPI == 3) {
                    const float2 rv = *(const float2*)(rz + row * (size_t)ldc + col);
                    vx = fmaf(g, vx, rv.x);
                    vy = fmaf(g, vy, rv.y);
                    *(float2*)(Cfz + row * (size_t)ldc + col) = make_float2(vx, vy);
                } else {  // EPI == 0: fp16 logits
                    *(__half2*)(Chz + row * (size_t)ldc + col) =
                        __floats2half2_rn(vx, vy);
                }
            }
        }
    }
}

// ---------------------------------------------------------------------------
// Convert fp32 array -> fp16. Grid-stride, float4 granularity.
// ---------------------------------------------------------------------------
__global__ void convert_f16(const float* __restrict__ x, half* __restrict__ o,
                            size_t n4)
{
    for (size_t i = blockIdx.x * (size_t)blockDim.x + threadIdx.x; i < n4;
         i += (size_t)gridDim.x * blockDim.x) {
        float4 v = ((const float4*)x)[i];
        ((__half2*)o)[2 * i] = __floats2half2_rn(v.x, v.y);
        ((__half2*)o)[2 * i + 1] = __floats2half2_rn(v.z, v.w);
    }
}

// ---------------------------------------------------------------------------
// Column softmax, in place, fp16 logits -> fp16 weights.
// Softmax over w (rows) per (batch, v column). block (32,16), grid (32, 8).
// ---------------------------------------------------------------------------
__global__ __launch_bounds__(512) void softmax_col(half* __restrict__ att)
{
    __shared__ float red[16][33];
    const int tx = threadIdx.x, ty = threadIdx.y;
    const size_t base = (size_t)blockIdx.y * VDIM * VDIM + (size_t)blockIdx.x * 32 + tx;

    float vals[64];
    float m = -INFINITY;
#pragma unroll
    for (int k = 0; k < 64; k++) {
        vals[k] = __half2float(att[base + (size_t)(ty + 16 * k) * VDIM]);
        m = fmaxf(m, vals[k]);
    }
    red[ty][tx] = m;
    __syncthreads();
#pragma unroll
    for (int off = 8; off >= 1; off >>= 1) {
        if (ty < off) red[ty][tx] = fmaxf(red[ty][tx], red[ty + off][tx]);
        __syncthreads();
    }
    m = red[0][tx];
    __syncthreads();

    float s = 0.f;
#pragma unroll
    for (int k = 0; k < 64; k++) {
        vals[k] = __expf(vals[k] - m);
        s += vals[k];
    }
    red[ty][tx] = s;
    __syncthreads();
#pragma unroll
    for (int off = 8; off >= 1; off >>= 1) {
        if (ty < off) red[ty][tx] += red[ty + off][tx];
        __syncthreads();
    }
    const float inv = 1.0f / red[0][tx];

#pragma unroll
    for (int k = 0; k < 64; k++) {
        const size_t idx = base + (size_t)(ty + 16 * k) * VDIM;
        att[idx] = __float2half_rn(vals[k] * inv);
    }
}

// ---------------------------------------------------------------------------
extern "C" void kernel_launch(void* const* d_in, const int* in_sizes, int n_in,
                              void* d_out, int out_size)
{
    const float* input = (const float*)d_in[0];
    const float* Wq    = (const float*)d_in[1];
    const float* bq    = (const float*)d_in[2];
    const float* Wk    = (const float*)d_in[3];
    const float* bk    = (const float*)d_in[4];
    const float* Wv    = (const float*)d_in[5];
    const float* bv    = (const float*)d_in[6];
    const float* gamma = (const float*)d_in[7];
    float* out = (float*)d_out;

    half *in_f16, *wq_f16, *wk_f16, *wv_f16, *qT, *kT, *v_f16, *att_f16;
    cudaGetSymbolAddress((void**)&in_f16, g_in_f16);
    cudaGetSymbolAddress((void**)&wq_f16, g_wq_f16);
    cudaGetSymbolAddress((void**)&wk_f16, g_wk_f16);
    cudaGetSymbolAddress((void**)&wv_f16, g_wv_f16);
    cudaGetSymbolAddress((void**)&qT, g_qT);
    cudaGetSymbolAddress((void**)&kT, g_kT);
    cudaGetSymbolAddress((void**)&v_f16, g_v_f16);
    cudaGetSymbolAddress((void**)&att_f16, g_att_f16);

    cudaFuncSetAttribute(gemm_f16<0>, cudaFuncAttributeMaxDynamicSharedMemorySize, SMEM_F16);
    cudaFuncSetAttribute(gemm_f16<1>, cudaFuncAttributeMaxDynamicSharedMemorySize, SMEM_F16);
    cudaFuncSetAttribute(gemm_f16<2>, cudaFuncAttributeMaxDynamicSharedMemorySize, SMEM_F16);
    cudaFuncSetAttribute(gemm_f16<3>, cudaFuncAttributeMaxDynamicSharedMemorySize, SMEM_F16);

    // Side stream for the independent v-branch (created once, outside capture).
    static cudaStream_t sv = nullptr;
    static cudaEvent_t evFork = nullptr, evJoin = nullptr;
    if (sv == nullptr) {
        cudaStreamCreateWithFlags(&sv, cudaStreamNonBlocking);
        cudaEventCreateWithFlags(&evFork, cudaEventDisableTiming);
        cudaEventCreateWithFlags(&evJoin, cudaEventDisableTiming);
    }

    const long long MN = (long long)BATCH * SEQ;   // 32768
    const long long BSEQ = (long long)SEQ * VDIM;  // 4194304
    const long long AT = (long long)VDIM * VDIM;   // 1048576

    // Conversions — input first (both branches need it)
    convert_f16<<<2048, 256>>>(input, in_f16, (size_t)MN * VDIM / 4);

    // Fork: v branch on side stream (wv convert + v GEMM)
    cudaEventRecord(evFork, 0);
    cudaStreamWaitEvent(sv, evFork, 0);
    convert_f16<<<256, 256, 0, sv>>>(Wv, wv_f16, (size_t)VDIM * VDIM / 4);
    gemm_f16<2><<<dim3(8, 256, 1), 256, SMEM_F16, sv>>>(
        in_f16, VDIM, 0, wv_f16, VDIM, 0,
        nullptr, v_f16, VDIM, 0, bv, nullptr, nullptr,
        nullptr, nullptr, nullptr, VDIM / 64);
    cudaEventRecord(evJoin, sv);

    // Main branch: q/k projections (merged), attn, softmax
    convert_f16<<<64, 256>>>(Wq, wq_f16, (size_t)VDIM * KQDIM / 4);
    convert_f16<<<64, 256>>>(Wk, wk_f16, (size_t)VDIM * KQDIM / 4);

    // Merged q/k: z=0 -> (Wq,bq,qT), z=1 -> (Wk,bk,kT).
    // (M=1024, N=32768, K=256) each.
    gemm_f16<1><<<dim3(256, 8, 2), 256, SMEM_F16>>>(
        wq_f16, KQDIM, 0,
        in_f16 + (VDIM - KQDIM), VDIM, 0,
        nullptr, qT, MN, 0, bq, nullptr, nullptr,
        wk_f16, bk, kT, KQDIM / 64);
    // attnT[b][w, v] = sum_n qT[w, bn] * kT[v, bn]  (per batch M=N=1024, K=4096)
    // fp16 logits out
    gemm_f16<0><<<dim3(8, 8, 8), 256, SMEM_F16>>>(
        qT, MN, SEQ, kT, MN, SEQ,
        nullptr, att_f16, VDIM, AT, nullptr, nullptr, nullptr,
        nullptr, nullptr, nullptr, SEQ / 64);
    // softmax over w, in place fp16
    softmax_col<<<dim3(VDIM / 32, BATCH), dim3(32, 16)>>>(att_f16);

    // Join: out GEMM needs v
    cudaStreamWaitEvent(0, evJoin, 0);
    // out[b][n, w] = gamma * sum_v v[bn, v] * att[b][w, v] + input
    gemm_f16<3><<<dim3(8, 32, 8), 256, SMEM_F16>>>(
        v_f16, VDIM, BSEQ, att_f16, VDIM, AT,
        out, nullptr, VDIM, BSEQ, nullptr, input, gamma,
        nullptr, nullptr, nullptr, VDIM / 64);
}

// round 13
// speedup vs baseline: 1.0154x; 1.0154x over previous
#include <cuda_runtime.h>
#include <cuda_fp16.h>
#include <cstdint>
#include <math.h>

// Problem constants
#define BATCH 8
#define SEQ   4096
#define VDIM  1024
#define KQDIM 256

// ---------------------------------------------------------------------------
// Scratch (device globals; no runtime allocation allowed) — all fp16 path
// ---------------------------------------------------------------------------
__device__ half g_in_f16[(size_t)BATCH * SEQ * VDIM];
__device__ half g_wq_f16[(size_t)VDIM * KQDIM];
__device__ half g_wk_f16[(size_t)VDIM * KQDIM];
__device__ half g_wv_f16[(size_t)VDIM * VDIM];
__device__ half g_qT[(size_t)VDIM * BATCH * SEQ];      // [1024 w][32768 n]
__device__ half g_kT[(size_t)VDIM * BATCH * SEQ];
__device__ half g_v_f16[(size_t)BATCH * SEQ * VDIM];   // [32768 n][1024 v]
__device__ half g_att_f16[(size_t)BATCH * VDIM * VDIM]; // logits then weights

// ---------------------------------------------------------------------------
// Helpers
// ---------------------------------------------------------------------------
__device__ __forceinline__ uint32_t smem_to_u32(const void* p) {
    uint32_t a;
    asm("{ .reg .u64 t; cvta.to.shared.u64 t, %1; cvt.u32.u64 %0, t; }"
        : "=r"(a) : "l"(p));
    return a;
}

__device__ __forceinline__ void ldsm_x4(uint32_t addr, uint32_t* r) {
    asm volatile("ldmatrix.sync.aligned.m8n8.x4.shared.b16 {%0,%1,%2,%3}, [%4];"
        : "=r"(r[0]), "=r"(r[1]), "=r"(r[2]), "=r"(r[3]) : "r"(addr));
}

__device__ __forceinline__ void mma_fp16(float* d, const uint32_t* a, const uint32_t* b) {
    asm volatile(
        "mma.sync.aligned.m16n8k16.row.col.f32.f16.f16.f32 "
        "{%0,%1,%2,%3}, {%4,%5,%6,%7}, {%8,%9}, {%0,%1,%2,%3};"
        : "+f"(d[0]), "+f"(d[1]), "+f"(d[2]), "+f"(d[3])
        : "r"(a[0]), "r"(a[1]), "r"(a[2]), "r"(a[3]), "r"(b[0]), "r"(b[1]));
}

#define CP_ASYNC16(s, g) \
    asm volatile("cp.async.cg.shared.global [%0], [%1], 16;" :: "r"(s), "l"(g))
#define CP_COMMIT() asm volatile("cp.async.commit_group;" ::: "memory")
#define CP_WAIT(n)  asm volatile("cp.async.wait_group %0;" :: "n"(n) : "memory")

// SMEM tile geometry: K-chunk 64 halfwords = 128B data + 16B pad = 144B rows.
#define ROWB 144
#define A_COMP (128 * ROWB)            // 18432 (128-row M tile)
#define B_COMP (128 * ROWB)            // 18432
#define STAGE_F16 (A_COMP + B_COMP)    // 36864
#define PIPE_F16 3
#define SMEM_F16 (PIPE_F16 * STAGE_F16)  // 110592 -> 2 CTAs/SM

// ---------------------------------------------------------------------------
// Unified fp16 NT GEMM: C = A * B^T, K-major fp16 operands.
// CTA tile 128x128, K-chunk 64, 3-stage cp.async, 256 threads, 8 warps
// (2x4), warp tile 64x32, fp32 accumulate, 2 CTAs/SM.
// Single-buffered fragments (compiler-scheduled) — R12's manual double
// buffering overflowed the 128-reg cap and spilled.
// EPI: 0 = fp16 store (attn logits)
//      1 = +bias[row] -> fp16; z selects {A,bias,Ch} vs {A2,bias2,Ch2} (q/k)
//      2 = +bias[col] -> fp16 (v projection)
//      3 = gamma*acc + resid -> fp32 (final output)
// ---------------------------------------------------------------------------
template <int EPI>
__global__ __launch_bounds__(256, 2) void gemm_f16(
    const half* __restrict__ A, long long lda, long long a_bs,
    const half* __restrict__ B, long long ldb, long long b_bs,
    float* __restrict__ Cf, half* __restrict__ Ch, long long ldc, long long c_bs,
    const float* __restrict__ bias,
    const float* __restrict__ resid,
    const float* __restrict__ gamma,
    const half* __restrict__ A2,
    const float* __restrict__ bias2,
    half* __restrict__ Ch2,
    int nchunks)
{
    extern __shared__ char smem[];
    const int tid = threadIdx.x;
    const int wid = tid >> 5;
    const int lane = tid & 31;

    const size_t m0 = (size_t)blockIdx.y * 128;
    const size_t n0 = (size_t)blockIdx.x * 128;
    const size_t z = blockIdx.z;
    if (EPI == 1) {
        if (z == 1) { A = A2; bias = bias2; Ch = Ch2; }
    } else {
        A += z * a_bs;
        B += z * b_bs;
    }

    // cp.async mapping: seg = tid&7 (16B of the 128B row), r = tid>>3 (0..31)
    const int seg = tid & 7;
    const int r = tid >> 3;
    const uint32_t sb = smem_to_u32(smem);

    const half* Ag[4];
    uint32_t Asm[4];
#pragma unroll
    for (int j = 0; j < 4; j++) {
        Ag[j] = A + (m0 + r + 32 * j) * (size_t)lda + seg * 8;
        Asm[j] = (r + 32 * j) * ROWB + seg * 16;
    }
    const half* Bg[4];
    uint32_t Bsm[4];
#pragma unroll
    for (int j = 0; j < 4; j++) {
        Bg[j] = B + (n0 + r + 32 * j) * (size_t)ldb + seg * 8;
        Bsm[j] = A_COMP + (r + 32 * j) * ROWB + seg * 16;
    }

    auto load_stage = [&](int kc, int s) {
        const uint32_t st = sb + s * STAGE_F16;
        const size_t ko = (size_t)kc * 64;
#pragma unroll
        for (int j = 0; j < 4; j++) CP_ASYNC16(st + Asm[j], Ag[j] + ko);
#pragma unroll
        for (int j = 0; j < 4; j++) CP_ASYNC16(st + Bsm[j], Bg[j] + ko);
        CP_COMMIT();
    };

    // Warp tile origin (8 warps: 2 x 4)
    const int wm = (wid >> 2) * 64;
    const int wn = (wid & 3) * 32;

    float acc[4][4][4];
#pragma unroll
    for (int i = 0; i < 4; i++)
#pragma unroll
        for (int j = 0; j < 4; j++)
#pragma unroll
            for (int k = 0; k < 4; k++) acc[i][j][k] = 0.f;

    const uint32_t lrow16 = lane & 15;
    const uint32_t lcol16 = (lane >> 4) * 16;

#pragma unroll
    for (int s = 0; s < PIPE_F16 - 1; s++) load_stage(s, s);

    for (int i = 0; i < nchunks; i++) {
        CP_WAIT(PIPE_F16 - 2);
        __syncthreads();

        if (i + PIPE_F16 - 1 < nchunks)
            load_stage(i + PIPE_F16 - 1, (i + PIPE_F16 - 1) % PIPE_F16);

        const uint32_t st = sb + (i % PIPE_F16) * STAGE_F16;
#pragma unroll
        for (int kk = 0; kk < 4; kk++) {
            const uint32_t kb = kk * 32 + lcol16;
            uint32_t Bf[4][2];
#pragma unroll
            for (int p = 0; p < 2; p++) {
                uint32_t bd = st + A_COMP + (wn + p * 16 + lrow16) * ROWB + kb;
                uint32_t t[4];
                ldsm_x4(bd, t);
                Bf[2 * p][0] = t[0]; Bf[2 * p][1] = t[2];
                Bf[2 * p + 1][0] = t[1]; Bf[2 * p + 1][1] = t[3];
            }
            uint32_t Af[4][4];
#pragma unroll
            for (int mt = 0; mt < 4; mt++) {
                uint32_t ad = st + (wm + mt * 16 + lrow16) * ROWB + kb;
                ldsm_x4(ad, Af[mt]);
            }
#pragma unroll
            for (int mt = 0; mt < 4; mt++)
#pragma unroll
                for (int nt = 0; nt < 4; nt++)
                    mma_fp16(acc[mt][nt], Af[mt], Bf[nt]);
        }
    }

    // Epilogue
    const int er = lane >> 2;
    const int ec = (lane & 3) * 2;
    const float g = (EPI == 3) ? __ldg(gamma) : 0.f;
    const float* rz = (EPI == 3) ? (resid + z * c_bs) : (const float*)nullptr;
    float* Cfz = (EPI == 3) ? (Cf + z * c_bs) : nullptr;
    half* Chz = (EPI == 1) ? Ch : ((EPI == 0 || EPI == 2) ? (Ch + z * c_bs) : nullptr);
#pragma unroll
    for (int mt = 0; mt < 4; mt++) {
#pragma unroll
        for (int half_i = 0; half_i < 2; half_i++) {
            const size_t row = m0 + wm + mt * 16 + er + half_i * 8;
            float rowbias = 0.f;
            if (EPI == 1) rowbias = bias[row];
#pragma unroll
            for (int nt = 0; nt < 4; nt++) {
                const size_t col = n0 + wn + nt * 8 + ec;
                float vx = acc[mt][nt][half_i * 2 + 0];
                float vy = acc[mt][nt][half_i * 2 + 1];
                if (EPI == 1) {
                    vx += rowbias; vy += rowbias;
                    *(__half2*)(Chz + row * (size_t)ldc + col) =
                        __floats2half2_rn(vx, vy);
                } else if (EPI == 2) {
                    vx += bias[col]; vy += bias[col + 1];
                    *(__half2*)(Chz + row * (size_t)ldc + col) =
                        __floats2half2_rn(vx, vy);
                } else if (EPI == 3) {
                    const float2 rv = *(const float2*)(rz + row * (size_t)ldc + col);
                    vx = fmaf(g, vx, rv.x);
                    vy = fmaf(g, vy, rv.y);
                    *(float2*)(Cfz + row * (size_t)ldc + col) = make_float2(vx, vy);
                } else {  // EPI == 0: fp16 logits
                    *(__half2*)(Chz + row * (size_t)ldc + col) =
                        __floats2half2_rn(vx, vy);
                }
            }
        }
    }
}

// ---------------------------------------------------------------------------
// Convert fp32 array -> fp16. Grid-stride, float4 granularity.
// ---------------------------------------------------------------------------
__global__ void convert_f16(const float* __restrict__ x, half* __restrict__ o,
                            size_t n4)
{
    for (size_t i = blockIdx.x * (size_t)blockDim.x + threadIdx.x; i < n4;
         i += (size_t)gridDim.x * blockDim.x) {
        float4 v = ((const float4*)x)[i];
        ((__half2*)o)[2 * i] = __floats2half2_rn(v.x, v.y);
        ((__half2*)o)[2 * i + 1] = __floats2half2_rn(v.z, v.w);
    }
}

// ---------------------------------------------------------------------------
// Column softmax, in place, fp16 logits -> fp16 weights.
// Softmax over w (rows) per (batch, v column). block (32,16), grid (32, 8).
// ---------------------------------------------------------------------------
__global__ __launch_bounds__(512) void softmax_col(half* __restrict__ att)
{
    __shared__ float red[16][33];
    const int tx = threadIdx.x, ty = threadIdx.y;
    const size_t base = (size_t)blockIdx.y * VDIM * VDIM + (size_t)blockIdx.x * 32 + tx;

    float vals[64];
    float m = -INFINITY;
#pragma unroll
    for (int k = 0; k < 64; k++) {
        vals[k] = __half2float(att[base + (size_t)(ty + 16 * k) * VDIM]);
        m = fmaxf(m, vals[k]);
    }
    red[ty][tx] = m;
    __syncthreads();
#pragma unroll
    for (int off = 8; off >= 1; off >>= 1) {
        if (ty < off) red[ty][tx] = fmaxf(red[ty][tx], red[ty + off][tx]);
        __syncthreads();
    }
    m = red[0][tx];
    __syncthreads();

    float s = 0.f;
#pragma unroll
    for (int k = 0; k < 64; k++) {
        vals[k] = __expf(vals[k] - m);
        s += vals[k];
    }
    red[ty][tx] = s;
    __syncthreads();
#pragma unroll
    for (int off = 8; off >= 1; off >>= 1) {
        if (ty < off) red[ty][tx] += red[ty + off][tx];
        __syncthreads();
    }
    const float inv = 1.0f / red[0][tx];

#pragma unroll
    for (int k = 0; k < 64; k++) {
        const size_t idx = base + (size_t)(ty + 16 * k) * VDIM;
        att[idx] = __float2half_rn(vals[k] * inv);
    }
}

// ---------------------------------------------------------------------------
extern "C" void kernel_launch(void* const* d_in, const int* in_sizes, int n_in,
                              void* d_out, int out_size)
{
    const float* input = (const float*)d_in[0];
    const float* Wq    = (const float*)d_in[1];
    const float* bq    = (const float*)d_in[2];
    const float* Wk    = (const float*)d_in[3];
    const float* bk    = (const float*)d_in[4];
    const float* Wv    = (const float*)d_in[5];
    const float* bv    = (const float*)d_in[6];
    const float* gamma = (const float*)d_in[7];
    float* out = (float*)d_out;

    half *in_f16, *wq_f16, *wk_f16, *wv_f16, *qT, *kT, *v_f16, *att_f16;
    cudaGetSymbolAddress((void**)&in_f16, g_in_f16);
    cudaGetSymbolAddress((void**)&wq_f16, g_wq_f16);
    cudaGetSymbolAddress((void**)&wk_f16, g_wk_f16);
    cudaGetSymbolAddress((void**)&wv_f16, g_wv_f16);
    cudaGetSymbolAddress((void**)&qT, g_qT);
    cudaGetSymbolAddress((void**)&kT, g_kT);
    cudaGetSymbolAddress((void**)&v_f16, g_v_f16);
    cudaGetSymbolAddress((void**)&att_f16, g_att_f16);

    cudaFuncSetAttribute(gemm_f16<0>, cudaFuncAttributeMaxDynamicSharedMemorySize, SMEM_F16);
    cudaFuncSetAttribute(gemm_f16<1>, cudaFuncAttributeMaxDynamicSharedMemorySize, SMEM_F16);
    cudaFuncSetAttribute(gemm_f16<2>, cudaFuncAttributeMaxDynamicSharedMemorySize, SMEM_F16);
    cudaFuncSetAttribute(gemm_f16<3>, cudaFuncAttributeMaxDynamicSharedMemorySize, SMEM_F16);

    // Side stream for the independent v-branch (created once, outside capture).
    static cudaStream_t sv = nullptr;
    static cudaEvent_t evFork = nullptr, evJoin = nullptr;
    if (sv == nullptr) {
        cudaStreamCreateWithFlags(&sv, cudaStreamNonBlocking);
        cudaEventCreateWithFlags(&evFork, cudaEventDisableTiming);
        cudaEventCreateWithFlags(&evJoin, cudaEventDisableTiming);
    }

    const long long MN = (long long)BATCH * SEQ;   // 32768
    const long long BSEQ = (long long)SEQ * VDIM;  // 4194304
    const long long AT = (long long)VDIM * VDIM;   // 1048576

    // Conversions — input first (both branches need it)
    convert_f16<<<2048, 256>>>(input, in_f16, (size_t)MN * VDIM / 4);

    // Fork: v branch on side stream (wv convert + v GEMM)
    cudaEventRecord(evFork, 0);
    cudaStreamWaitEvent(sv, evFork, 0);
    convert_f16<<<256, 256, 0, sv>>>(Wv, wv_f16, (size_t)VDIM * VDIM / 4);
    gemm_f16<2><<<dim3(8, 256, 1), 256, SMEM_F16, sv>>>(
        in_f16, VDIM, 0, wv_f16, VDIM, 0,
        nullptr, v_f16, VDIM, 0, bv, nullptr, nullptr,
        nullptr, nullptr, nullptr, VDIM / 64);
    cudaEventRecord(evJoin, sv);

    // Main branch: q/k projections (merged), attn, softmax
    convert_f16<<<64, 256>>>(Wq, wq_f16, (size_t)VDIM * KQDIM / 4);
    convert_f16<<<64, 256>>>(Wk, wk_f16, (size_t)VDIM * KQDIM / 4);

    // Merged q/k: z=0 -> (Wq,bq,qT), z=1 -> (Wk,bk,kT).
    // (M=1024, N=32768, K=256) each.
    gemm_f16<1><<<dim3(256, 8, 2), 256, SMEM_F16>>>(
        wq_f16, KQDIM, 0,
        in_f16 + (VDIM - KQDIM), VDIM, 0,
        nullptr, qT, MN, 0, bq, nullptr, nullptr,
        wk_f16, bk, kT, KQDIM / 64);
    // attnT[b][w, v] = sum_n qT[w, bn] * kT[v, bn]  (per batch M=N=1024, K=4096)
    // fp16 logits out
    gemm_f16<0><<<dim3(8, 8, 8), 256, SMEM_F16>>>(
        qT, MN, SEQ, kT, MN, SEQ,
        nullptr, att_f16, VDIM, AT, nullptr, nullptr, nullptr,
        nullptr, nullptr, nullptr, SEQ / 64);
    // softmax over w, in place fp16
    softmax_col<<<dim3(VDIM / 32, BATCH), dim3(32, 16)>>>(att_f16);

    // Join: out GEMM needs v
    cudaStreamWaitEvent(0, evJoin, 0);
    // out[b][n, w] = gamma * sum_v v[bn, v] * att[b][w, v] + input
    gemm_f16<3><<<dim3(8, 32, 8), 256, SMEM_F16>>>(
        v_f16, VDIM, BSEQ, att_f16, VDIM, AT,
        out, nullptr, VDIM, BSEQ, nullptr, input, gamma,
        nullptr, nullptr, nullptr, VDIM / 64);
}

// round 14
// speedup vs baseline: 1.0291x; 1.0135x over previous
#include <cuda_runtime.h>
#include <cuda_fp16.h>
#include <cstdint>
#include <math.h>

// Problem constants
#define BATCH 8
#define SEQ   4096
#define VDIM  1024
#define KQDIM 256

// ---------------------------------------------------------------------------
// Scratch (device globals; no runtime allocation allowed) — all fp16 path
// ---------------------------------------------------------------------------
__device__ half g_in_f16[(size_t)BATCH * SEQ * VDIM];
__device__ half g_wq_f16[(size_t)VDIM * KQDIM];
__device__ half g_wk_f16[(size_t)VDIM * KQDIM];
__device__ half g_wv_f16[(size_t)VDIM * VDIM];
__device__ half g_qT[(size_t)VDIM * BATCH * SEQ];      // [1024 w][32768 n]
__device__ half g_kT[(size_t)VDIM * BATCH * SEQ];
__device__ half g_v_f16[(size_t)BATCH * SEQ * VDIM];   // [32768 n][1024 v]
__device__ half g_att_f16[(size_t)BATCH * VDIM * VDIM]; // logits then weights

// ---------------------------------------------------------------------------
// Helpers
// ---------------------------------------------------------------------------
__device__ __forceinline__ uint32_t smem_to_u32(const void* p) {
    uint32_t a;
    asm("{ .reg .u64 t; cvta.to.shared.u64 t, %1; cvt.u32.u64 %0, t; }"
        : "=r"(a) : "l"(p));
    return a;
}

__device__ __forceinline__ void ldsm_x4(uint32_t addr, uint32_t* r) {
    asm volatile("ldmatrix.sync.aligned.m8n8.x4.shared.b16 {%0,%1,%2,%3}, [%4];"
        : "=r"(r[0]), "=r"(r[1]), "=r"(r[2]), "=r"(r[3]) : "r"(addr));
}

__device__ __forceinline__ void mma_fp16(float* d, const uint32_t* a, const uint32_t* b) {
    asm volatile(
        "mma.sync.aligned.m16n8k16.row.col.f32.f16.f16.f32 "
        "{%0,%1,%2,%3}, {%4,%5,%6,%7}, {%8,%9}, {%0,%1,%2,%3};"
        : "+f"(d[0]), "+f"(d[1]), "+f"(d[2]), "+f"(d[3])
        : "r"(a[0]), "r"(a[1]), "r"(a[2]), "r"(a[3]), "r"(b[0]), "r"(b[1]));
}

#define CP_ASYNC16(s, g) \
    asm volatile("cp.async.cg.shared.global [%0], [%1], 16;" :: "r"(s), "l"(g))
#define CP_COMMIT() asm volatile("cp.async.commit_group;" ::: "memory")
#define CP_WAIT(n)  asm volatile("cp.async.wait_group %0;" :: "n"(n) : "memory")

// SMEM tile geometry: K-chunk 64 halfwords = 128B data + 16B pad = 144B rows.
#define ROWB 144
#define A_COMP (128 * ROWB)            // 18432 (128-row M tile)
#define B_COMP (128 * ROWB)            // 18432
#define STAGE_F16 (A_COMP + B_COMP)    // 36864
#define PIPE_F16 3
#define SMEM_F16 (PIPE_F16 * STAGE_F16)  // 110592 -> 2 CTAs/SM

// ---------------------------------------------------------------------------
// Unified fp16 NT GEMM: C = A * B^T, K-major fp16 operands.
// CTA tile 128x128, K-chunk 64, 3-stage cp.async, 256 threads, 8 warps
// (2x4), warp tile 64x32, fp32 accumulate, 2 CTAs/SM.
// Single-buffered fragments (compiler-scheduled; manual double-buffering
// spills past the 128-reg cap — measured regression in R12).
// EPI: 0 = fp16 store (attn logits)
//      1 = +bias[row] -> fp16; z selects {A,bias,Ch} vs {A2,bias2,Ch2} (q/k)
//      2 = +bias[col] -> fp16 (v projection)
//      3 = gamma*acc + resid -> fp32 (final output)
// ---------------------------------------------------------------------------
template <int EPI>
__global__ __launch_bounds__(256, 2) void gemm_f16(
    const half* __restrict__ A, long long lda, long long a_bs,
    const half* __restrict__ B, long long ldb, long long b_bs,
    float* __restrict__ Cf, half* __restrict__ Ch, long long ldc, long long c_bs,
    const float* __restrict__ bias,
    const float* __restrict__ resid,
    const float* __restrict__ gamma,
    const half* __restrict__ A2,
    const float* __restrict__ bias2,
    half* __restrict__ Ch2,
    int nchunks)
{
    extern __shared__ char smem[];
    const int tid = threadIdx.x;
    const int wid = tid >> 5;
    const int lane = tid & 31;

    const size_t m0 = (size_t)blockIdx.y * 128;
    const size_t n0 = (size_t)blockIdx.x * 128;
    const size_t z = blockIdx.z;
    if (EPI == 1) {
        if (z == 1) { A = A2; bias = bias2; Ch = Ch2; }
    } else {
        A += z * a_bs;
        B += z * b_bs;
    }

    // cp.async mapping: seg = tid&7 (16B of the 128B row), r = tid>>3 (0..31)
    const int seg = tid & 7;
    const int r = tid >> 3;
    const uint32_t sb = smem_to_u32(smem);

    const half* Ag[4];
    uint32_t Asm[4];
#pragma unroll
    for (int j = 0; j < 4; j++) {
        Ag[j] = A + (m0 + r + 32 * j) * (size_t)lda + seg * 8;
        Asm[j] = (r + 32 * j) * ROWB + seg * 16;
    }
    const half* Bg[4];
    uint32_t Bsm[4];
#pragma unroll
    for (int j = 0; j < 4; j++) {
        Bg[j] = B + (n0 + r + 32 * j) * (size_t)ldb + seg * 8;
        Bsm[j] = A_COMP + (r + 32 * j) * ROWB + seg * 16;
    }

    auto load_stage = [&](int kc, int s) {
        const uint32_t st = sb + s * STAGE_F16;
        const size_t ko = (size_t)kc * 64;
#pragma unroll
        for (int j = 0; j < 4; j++) CP_ASYNC16(st + Asm[j], Ag[j] + ko);
#pragma unroll
        for (int j = 0; j < 4; j++) CP_ASYNC16(st + Bsm[j], Bg[j] + ko);
        CP_COMMIT();
    };

    // Warp tile origin (8 warps: 2 x 4)
    const int wm = (wid >> 2) * 64;
    const int wn = (wid & 3) * 32;

    float acc[4][4][4];
#pragma unroll
    for (int i = 0; i < 4; i++)
#pragma unroll
        for (int j = 0; j < 4; j++)
#pragma unroll
            for (int k = 0; k < 4; k++) acc[i][j][k] = 0.f;

    const uint32_t lrow16 = lane & 15;
    const uint32_t lcol16 = (lane >> 4) * 16;

#pragma unroll
    for (int s = 0; s < PIPE_F16 - 1; s++) load_stage(s, s);

    for (int i = 0; i < nchunks; i++) {
        CP_WAIT(PIPE_F16 - 2);
        __syncthreads();

        if (i + PIPE_F16 - 1 < nchunks)
            load_stage(i + PIPE_F16 - 1, (i + PIPE_F16 - 1) % PIPE_F16);

        const uint32_t st = sb + (i % PIPE_F16) * STAGE_F16;
#pragma unroll
        for (int kk = 0; kk < 4; kk++) {
            const uint32_t kb = kk * 32 + lcol16;
            uint32_t Bf[4][2];
#pragma unroll
            for (int p = 0; p < 2; p++) {
                uint32_t bd = st + A_COMP + (wn + p * 16 + lrow16) * ROWB + kb;
                uint32_t t[4];
                ldsm_x4(bd, t);
                Bf[2 * p][0] = t[0]; Bf[2 * p][1] = t[2];
                Bf[2 * p + 1][0] = t[1]; Bf[2 * p + 1][1] = t[3];
            }
            uint32_t Af[4][4];
#pragma unroll
            for (int mt = 0; mt < 4; mt++) {
                uint32_t ad = st + (wm + mt * 16 + lrow16) * ROWB + kb;
                ldsm_x4(ad, Af[mt]);
            }
#pragma unroll
            for (int mt = 0; mt < 4; mt++)
#pragma unroll
                for (int nt = 0; nt < 4; nt++)
                    mma_fp16(acc[mt][nt], Af[mt], Bf[nt]);
        }
    }

    // Epilogue
    const int er = lane >> 2;
    const int ec = (lane & 3) * 2;
    const float g = (EPI == 3) ? __ldg(gamma) : 0.f;
    const float* rz = (EPI == 3) ? (resid + z * c_bs) : (const float*)nullptr;
    float* Cfz = (EPI == 3) ? (Cf + z * c_bs) : nullptr;
    half* Chz = (EPI == 1) ? Ch : ((EPI == 0 || EPI == 2) ? (Ch + z * c_bs) : nullptr);
#pragma unroll
    for (int mt = 0; mt < 4; mt++) {
#pragma unroll
        for (int half_i = 0; half_i < 2; half_i++) {
            const size_t row = m0 + wm + mt * 16 + er + half_i * 8;
            float rowbias = 0.f;
            if (EPI == 1) rowbias = bias[row];
#pragma unroll
            for (int nt = 0; nt < 4; nt++) {
                const size_t col = n0 + wn + nt * 8 + ec;
                float vx = acc[mt][nt][half_i * 2 + 0];
                float vy = acc[mt][nt][half_i * 2 + 1];
                if (EPI == 1) {
                    vx += rowbias; vy += rowbias;
                    *(__half2*)(Chz + row * (size_t)ldc + col) =
                        __floats2half2_rn(vx, vy);
                } else if (EPI == 2) {
                    vx += bias[col]; vy += bias[col + 1];
                    *(__half2*)(Chz + row * (size_t)ldc + col) =
                        __floats2half2_rn(vx, vy);
                } else if (EPI == 3) {
                    const float2 rv = *(const float2*)(rz + row * (size_t)ldc + col);
                    vx = fmaf(g, vx, rv.x);
                    vy = fmaf(g, vy, rv.y);
                    *(float2*)(Cfz + row * (size_t)ldc + col) = make_float2(vx, vy);
                } else {  // EPI == 0: fp16 logits
                    *(__half2*)(Chz + row * (size_t)ldc + col) =
                        __floats2half2_rn(vx, vy);
                }
            }
        }
    }
}

// ---------------------------------------------------------------------------
// Convert fp32 array -> fp16. Grid-stride, float4 granularity.
// ---------------------------------------------------------------------------
__global__ void convert_f16(const float* __restrict__ x, half* __restrict__ o,
                            size_t n4)
{
    for (size_t i = blockIdx.x * (size_t)blockDim.x + threadIdx.x; i < n4;
         i += (size_t)gridDim.x * blockDim.x) {
        float4 v = ((const float4*)x)[i];
        ((__half2*)o)[2 * i] = __floats2half2_rn(v.x, v.y);
        ((__half2*)o)[2 * i + 1] = __floats2half2_rn(v.z, v.w);
    }
}

// ---------------------------------------------------------------------------
// Convert a column slab [c0, c0+cols) of a [rows x VDIM] fp32 matrix into the
// same slab of the fp16 matrix. float4 granularity (cols multiple of 4).
// ---------------------------------------------------------------------------
__global__ void convert_f16_slab(const float* __restrict__ x,
                                 half* __restrict__ o,
                                 int c0, int cols, size_t rows)
{
    const size_t n4 = rows * (size_t)(cols / 4);
    const int c4 = cols / 4;
    for (size_t i = blockIdx.x * (size_t)blockDim.x + threadIdx.x; i < n4;
         i += (size_t)gridDim.x * blockDim.x) {
        const size_t row = i / c4;
        const int col4 = (int)(i % c4);
        const size_t off = row * VDIM + c0 + col4 * 4;
        float4 v = *(const float4*)(x + off);
        *(__half2*)(o + off) = __floats2half2_rn(v.x, v.y);
        *(__half2*)(o + off + 2) = __floats2half2_rn(v.z, v.w);
    }
}

// ---------------------------------------------------------------------------
// Column softmax, in place, fp16 logits -> fp16 weights.
// Softmax over w (rows) per (batch, v column). block (32,16), grid (32, 8).
// ---------------------------------------------------------------------------
__global__ __launch_bounds__(512) void softmax_col(half* __restrict__ att)
{
    __shared__ float red[16][33];
    const int tx = threadIdx.x, ty = threadIdx.y;
    const size_t base = (size_t)blockIdx.y * VDIM * VDIM + (size_t)blockIdx.x * 32 + tx;

    float vals[64];
    float m = -INFINITY;
#pragma unroll
    for (int k = 0; k < 64; k++) {
        vals[k] = __half2float(att[base + (size_t)(ty + 16 * k) * VDIM]);
        m = fmaxf(m, vals[k]);
    }
    red[ty][tx] = m;
    __syncthreads();
#pragma unroll
    for (int off = 8; off >= 1; off >>= 1) {
        if (ty < off) red[ty][tx] = fmaxf(red[ty][tx], red[ty + off][tx]);
        __syncthreads();
    }
    m = red[0][tx];
    __syncthreads();

    float s = 0.f;
#pragma unroll
    for (int k = 0; k < 64; k++) {
        vals[k] = __expf(vals[k] - m);
        s += vals[k];
    }
    red[ty][tx] = s;
    __syncthreads();
#pragma unroll
    for (int off = 8; off >= 1; off >>= 1) {
        if (ty < off) red[ty][tx] += red[ty + off][tx];
        __syncthreads();
    }
    const float inv = 1.0f / red[0][tx];

#pragma unroll
    for (int k = 0; k < 64; k++) {
        const size_t idx = base + (size_t)(ty + 16 * k) * VDIM;
        att[idx] = __float2half_rn(vals[k] * inv);
    }
}

// ---------------------------------------------------------------------------
extern "C" void kernel_launch(void* const* d_in, const int* in_sizes, int n_in,
                              void* d_out, int out_size)
{
    const float* input = (const float*)d_in[0];
    const float* Wq    = (const float*)d_in[1];
    const float* bq    = (const float*)d_in[2];
    const float* Wk    = (const float*)d_in[3];
    const float* bk    = (const float*)d_in[4];
    const float* Wv    = (const float*)d_in[5];
    const float* bv    = (const float*)d_in[6];
    const float* gamma = (const float*)d_in[7];
    float* out = (float*)d_out;

    half *in_f16, *wq_f16, *wk_f16, *wv_f16, *qT, *kT, *v_f16, *att_f16;
    cudaGetSymbolAddress((void**)&in_f16, g_in_f16);
    cudaGetSymbolAddress((void**)&wq_f16, g_wq_f16);
    cudaGetSymbolAddress((void**)&wk_f16, g_wk_f16);
    cudaGetSymbolAddress((void**)&wv_f16, g_wv_f16);
    cudaGetSymbolAddress((void**)&qT, g_qT);
    cudaGetSymbolAddress((void**)&kT, g_kT);
    cudaGetSymbolAddress((void**)&v_f16, g_v_f16);
    cudaGetSymbolAddress((void**)&att_f16, g_att_f16);

    cudaFuncSetAttribute(gemm_f16<0>, cudaFuncAttributeMaxDynamicSharedMemorySize, SMEM_F16);
    cudaFuncSetAttribute(gemm_f16<1>, cudaFuncAttributeMaxDynamicSharedMemorySize, SMEM_F16);
    cudaFuncSetAttribute(gemm_f16<2>, cudaFuncAttributeMaxDynamicSharedMemorySize, SMEM_F16);
    cudaFuncSetAttribute(gemm_f16<3>, cudaFuncAttributeMaxDynamicSharedMemorySize, SMEM_F16);

    // Side stream for the independent v-branch (created once, outside capture).
    static cudaStream_t sv = nullptr;
    static cudaEvent_t evFork = nullptr, evJoin = nullptr, evSlab = nullptr;
    if (sv == nullptr) {
        cudaStreamCreateWithFlags(&sv, cudaStreamNonBlocking);
        cudaEventCreateWithFlags(&evFork, cudaEventDisableTiming);
        cudaEventCreateWithFlags(&evJoin, cudaEventDisableTiming);
        cudaEventCreateWithFlags(&evSlab, cudaEventDisableTiming);
    }

    const long long MN = (long long)BATCH * SEQ;   // 32768
    const long long BSEQ = (long long)SEQ * VDIM;  // 4194304
    const long long AT = (long long)VDIM * VDIM;   // 1048576

    // Fork side stream at entry.
    cudaEventRecord(evFork, 0);
    cudaStreamWaitEvent(sv, evFork, 0);

    // Main stream: convert ONLY the KQ slab (cols 768..1023) of input — this
    // is all the q/k GEMM needs; it unblocks the main branch ~3/4 sooner.
    convert_f16_slab<<<512, 256>>>(input, in_f16, VDIM - KQDIM, KQDIM, (size_t)MN);
    cudaEventRecord(evSlab, 0);

    // Side stream: Wv + the remaining input columns (0..767), then v GEMM
    // (which also needs the slab -> wait on evSlab).
    convert_f16<<<256, 256, 0, sv>>>(Wv, wv_f16, (size_t)VDIM * VDIM / 4);
    convert_f16_slab<<<1536, 256, 0, sv>>>(input, in_f16, 0, VDIM - KQDIM, (size_t)MN);
    cudaStreamWaitEvent(sv, evSlab, 0);
    gemm_f16<2><<<dim3(8, 256, 1), 256, SMEM_F16, sv>>>(
        in_f16, VDIM, 0, wv_f16, VDIM, 0,
        nullptr, v_f16, VDIM, 0, bv, nullptr, nullptr,
        nullptr, nullptr, nullptr, VDIM / 64);
    cudaEventRecord(evJoin, sv);

    // Main branch: weight converts, merged q/k, attn, softmax
    convert_f16<<<64, 256>>>(Wq, wq_f16, (size_t)VDIM * KQDIM / 4);
    convert_f16<<<64, 256>>>(Wk, wk_f16, (size_t)VDIM * KQDIM / 4);

    // Merged q/k: z=0 -> (Wq,bq,qT), z=1 -> (Wk,bk,kT). (M=1024,N=32768,K=256)
    gemm_f16<1><<<dim3(256, 8, 2), 256, SMEM_F16>>>(
        wq_f16, KQDIM, 0,
        in_f16 + (VDIM - KQDIM), VDIM, 0,
        nullptr, qT, MN, 0, bq, nullptr, nullptr,
        wk_f16, bk, kT, KQDIM / 64);
    // attnT[b][w, v] = sum_n qT[w, bn] * kT[v, bn]  (per batch M=N=1024, K=4096)
    gemm_f16<0><<<dim3(8, 8, 8), 256, SMEM_F16>>>(
        qT, MN, SEQ, kT, MN, SEQ,
        nullptr, att_f16, VDIM, AT, nullptr, nullptr, nullptr,
        nullptr, nullptr, nullptr, SEQ / 64);
    // softmax over w, in place fp16
    softmax_col<<<dim3(VDIM / 32, BATCH), dim3(32, 16)>>>(att_f16);

    // Join: out GEMM needs v
    cudaStreamWaitEvent(0, evJoin, 0);
    // out[b][n, w] = gamma * sum_v v[bn, v] * att[b][w, v] + input
    gemm_f16<3><<<dim3(8, 32, 8), 256, SMEM_F16>>>(
        v_f16, VDIM, BSEQ, att_f16, VDIM, AT,
        out, nullptr, VDIM, BSEQ, nullptr, input, gamma,
        nullptr, nullptr, nullptr, VDIM / 64);
}

// round 16
// speedup vs baseline: 1.0615x; 1.0314x over previous
#include <cuda_runtime.h>
#include <cuda_fp16.h>
#include <cstdint>
#include <math.h>

// Problem constants
#define BATCH 8
#define SEQ   4096
#define VDIM  1024
#define KQDIM 256

// ---------------------------------------------------------------------------
// Scratch (device globals; no runtime allocation allowed) — all fp16 path
// ---------------------------------------------------------------------------
__device__ half g_in_f16[(size_t)BATCH * SEQ * VDIM];
__device__ half g_wq_f16[(size_t)VDIM * KQDIM];
__device__ half g_wk_f16[(size_t)VDIM * KQDIM];
__device__ half g_wv_f16[(size_t)VDIM * VDIM];
__device__ half g_qT[(size_t)VDIM * BATCH * SEQ];      // [1024 w][32768 n]
__device__ half g_kT[(size_t)VDIM * BATCH * SEQ];
__device__ half g_v_f16[(size_t)BATCH * SEQ * VDIM];   // [32768 n][1024 v]
__device__ half g_att_f16[(size_t)BATCH * VDIM * VDIM]; // logits then weights

// ---------------------------------------------------------------------------
// Helpers
// ---------------------------------------------------------------------------
__device__ __forceinline__ uint32_t smem_to_u32(const void* p) {
    uint32_t a;
    asm("{ .reg .u64 t; cvta.to.shared.u64 t, %1; cvt.u32.u64 %0, t; }"
        : "=r"(a) : "l"(p));
    return a;
}

__device__ __forceinline__ void ldsm_x4(uint32_t addr, uint32_t* r) {
    asm volatile("ldmatrix.sync.aligned.m8n8.x4.shared.b16 {%0,%1,%2,%3}, [%4];"
        : "=r"(r[0]), "=r"(r[1]), "=r"(r[2]), "=r"(r[3]) : "r"(addr));
}

__device__ __forceinline__ void mma_fp16(float* d, const uint32_t* a, const uint32_t* b) {
    asm volatile(
        "mma.sync.aligned.m16n8k16.row.col.f32.f16.f16.f32 "
        "{%0,%1,%2,%3}, {%4,%5,%6,%7}, {%8,%9}, {%0,%1,%2,%3};"
        : "+f"(d[0]), "+f"(d[1]), "+f"(d[2]), "+f"(d[3])
        : "r"(a[0]), "r"(a[1]), "r"(a[2]), "r"(a[3]), "r"(b[0]), "r"(b[1]));
}

#define CP_ASYNC16(s, g) \
    asm volatile("cp.async.cg.shared.global [%0], [%1], 16;" :: "r"(s), "l"(g))
#define CP_COMMIT() asm volatile("cp.async.commit_group;" ::: "memory")
#define CP_WAIT(n)  asm volatile("cp.async.wait_group %0;" :: "n"(n) : "memory")

// SMEM tile geometry: K-chunk 64 halfwords = 128B data + 16B pad = 144B rows.
#define ROWB 144
#define A_COMP (128 * ROWB)            // 18432 (128-row M tile)
#define B_COMP (128 * ROWB)            // 18432
#define STAGE_F16 (A_COMP + B_COMP)    // 36864
#define PIPE_F16 3
#define SMEM_F16 (PIPE_F16 * STAGE_F16)  // 110592 -> 2 CTAs/SM

// ---------------------------------------------------------------------------
// Unified fp16 NT GEMM (fp32 accumulate — fp16 acc measured 3.7e-2 rel_err
// in R15, unusable at K>=1024): C = A * B^T, K-major fp16 operands.
// CTA tile 128x128, K-chunk 64, 3-stage cp.async, 256 threads, 8 warps
// (2x4), warp tile 64x32, 2 CTAs/SM.
// EPI: 0 = fp16 store (attn logits)
//      1 = +bias[row] -> fp16; z selects {A,bias,Ch} vs {A2,bias2,Ch2} (q/k)
//      2 = +bias[col] -> fp16 (v projection)
//      3 = gamma*acc + resid -> fp32 (final output)
// ---------------------------------------------------------------------------
template <int EPI>
__global__ __launch_bounds__(256, 2) void gemm_f16(
    const half* __restrict__ A, long long lda, long long a_bs,
    const half* __restrict__ B, long long ldb, long long b_bs,
    float* __restrict__ Cf, half* __restrict__ Ch, long long ldc, long long c_bs,
    const float* __restrict__ bias,
    const float* __restrict__ resid,
    const float* __restrict__ gamma,
    const half* __restrict__ A2,
    const float* __restrict__ bias2,
    half* __restrict__ Ch2,
    int nchunks)
{
    extern __shared__ char smem[];
    const int tid = threadIdx.x;
    const int wid = tid >> 5;
    const int lane = tid & 31;

    const size_t m0 = (size_t)blockIdx.y * 128;
    const size_t n0 = (size_t)blockIdx.x * 128;
    const size_t z = blockIdx.z;
    if (EPI == 1) {
        if (z == 1) { A = A2; bias = bias2; Ch = Ch2; }
    } else {
        A += z * a_bs;
        B += z * b_bs;
    }

    const int seg = tid & 7;
    const int r = tid >> 3;
    const uint32_t sb = smem_to_u32(smem);

    const half* Ag[4];
    uint32_t Asm[4];
#pragma unroll
    for (int j = 0; j < 4; j++) {
        Ag[j] = A + (m0 + r + 32 * j) * (size_t)lda + seg * 8;
        Asm[j] = (r + 32 * j) * ROWB + seg * 16;
    }
    const half* Bg[4];
    uint32_t Bsm[4];
#pragma unroll
    for (int j = 0; j < 4; j++) {
        Bg[j] = B + (n0 + r + 32 * j) * (size_t)ldb + seg * 8;
        Bsm[j] = A_COMP + (r + 32 * j) * ROWB + seg * 16;
    }

    auto load_stage = [&](int kc, int s) {
        const uint32_t st = sb + s * STAGE_F16;
        const size_t ko = (size_t)kc * 64;
#pragma unroll
        for (int j = 0; j < 4; j++) CP_ASYNC16(st + Asm[j], Ag[j] + ko);
#pragma unroll
        for (int j = 0; j < 4; j++) CP_ASYNC16(st + Bsm[j], Bg[j] + ko);
        CP_COMMIT();
    };

    const int wm = (wid >> 2) * 64;
    const int wn = (wid & 3) * 32;

    float acc[4][4][4];
#pragma unroll
    for (int i = 0; i < 4; i++)
#pragma unroll
        for (int j = 0; j < 4; j++)
#pragma unroll
            for (int k = 0; k < 4; k++) acc[i][j][k] = 0.f;

    const uint32_t lrow16 = lane & 15;
    const uint32_t lcol16 = (lane >> 4) * 16;

#pragma unroll
    for (int s = 0; s < PIPE_F16 - 1; s++) load_stage(s, s);

    for (int i = 0; i < nchunks; i++) {
        CP_WAIT(PIPE_F16 - 2);
        __syncthreads();

        if (i + PIPE_F16 - 1 < nchunks)
            load_stage(i + PIPE_F16 - 1, (i + PIPE_F16 - 1) % PIPE_F16);

        const uint32_t st = sb + (i % PIPE_F16) * STAGE_F16;
#pragma unroll
        for (int kk = 0; kk < 4; kk++) {
            const uint32_t kb = kk * 32 + lcol16;
            uint32_t Bf[4][2];
#pragma unroll
            for (int p = 0; p < 2; p++) {
                uint32_t bd = st + A_COMP + (wn + p * 16 + lrow16) * ROWB + kb;
                uint32_t t[4];
                ldsm_x4(bd, t);
                Bf[2 * p][0] = t[0]; Bf[2 * p][1] = t[2];
                Bf[2 * p + 1][0] = t[1]; Bf[2 * p + 1][1] = t[3];
            }
            uint32_t Af[4][4];
#pragma unroll
            for (int mt = 0; mt < 4; mt++) {
                uint32_t ad = st + (wm + mt * 16 + lrow16) * ROWB + kb;
                ldsm_x4(ad, Af[mt]);
            }
#pragma unroll
            for (int mt = 0; mt < 4; mt++)
#pragma unroll
                for (int nt = 0; nt < 4; nt++)
                    mma_fp16(acc[mt][nt], Af[mt], Bf[nt]);
        }
    }

    // Epilogue
    const int er = lane >> 2;
    const int ec = (lane & 3) * 2;
    const float g = (EPI == 3) ? __ldg(gamma) : 0.f;
    const float* rz = (EPI == 3) ? (resid + z * c_bs) : (const float*)nullptr;
    float* Cfz = (EPI == 3) ? (Cf + z * c_bs) : nullptr;
    half* Chz = (EPI == 1) ? Ch : ((EPI == 0 || EPI == 2) ? (Ch + z * c_bs) : nullptr);
#pragma unroll
    for (int mt = 0; mt < 4; mt++) {
#pragma unroll
        for (int half_i = 0; half_i < 2; half_i++) {
            const size_t row = m0 + wm + mt * 16 + er + half_i * 8;
            float rowbias = 0.f;
            if (EPI == 1) rowbias = bias[row];
#pragma unroll
            for (int nt = 0; nt < 4; nt++) {
                const size_t col = n0 + wn + nt * 8 + ec;
                float vx = acc[mt][nt][half_i * 2 + 0];
                float vy = acc[mt][nt][half_i * 2 + 1];
                if (EPI == 1) {
                    vx += rowbias; vy += rowbias;
                    *(__half2*)(Chz + row * (size_t)ldc + col) =
                        __floats2half2_rn(vx, vy);
                } else if (EPI == 2) {
                    vx += bias[col]; vy += bias[col + 1];
                    *(__half2*)(Chz + row * (size_t)ldc + col) =
                        __floats2half2_rn(vx, vy);
                } else if (EPI == 3) {
                    const float2 rv = *(const float2*)(rz + row * (size_t)ldc + col);
                    vx = fmaf(g, vx, rv.x);
                    vy = fmaf(g, vy, rv.y);
                    *(float2*)(Cfz + row * (size_t)ldc + col) = make_float2(vx, vy);
                } else {  // EPI == 0: fp16 logits
                    *(__half2*)(Chz + row * (size_t)ldc + col) =
                        __floats2half2_rn(vx, vy);
                }
            }
        }
    }
}

// ---------------------------------------------------------------------------
// Convert fp32 array -> fp16. Grid-stride, float4 granularity.
// ---------------------------------------------------------------------------
__global__ void convert_f16(const float* __restrict__ x, half* __restrict__ o,
                            size_t n4)
{
    for (size_t i = blockIdx.x * (size_t)blockDim.x + threadIdx.x; i < n4;
         i += (size_t)gridDim.x * blockDim.x) {
        float4 v = ((const float4*)x)[i];
        ((__half2*)o)[2 * i] = __floats2half2_rn(v.x, v.y);
        ((__half2*)o)[2 * i + 1] = __floats2half2_rn(v.z, v.w);
    }
}

// ---------------------------------------------------------------------------
// Convert a column slab [c0, c0+cols) of a [rows x VDIM] fp32 matrix.
// ---------------------------------------------------------------------------
__global__ void convert_f16_slab(const float* __restrict__ x,
                                 half* __restrict__ o,
                                 int c0, int cols, size_t rows)
{
    const size_t n4 = rows * (size_t)(cols / 4);
    const int c4 = cols / 4;
    for (size_t i = blockIdx.x * (size_t)blockDim.x + threadIdx.x; i < n4;
         i += (size_t)gridDim.x * blockDim.x) {
        const size_t row = i / c4;
        const int col4 = (int)(i % c4);
        const size_t off = row * VDIM + c0 + col4 * 4;
        float4 v = *(const float4*)(x + off);
        *(__half2*)(o + off) = __floats2half2_rn(v.x, v.y);
        *(__half2*)(o + off + 2) = __floats2half2_rn(v.z, v.w);
    }
}

// ---------------------------------------------------------------------------
// Column softmax, in place, fp16 logits -> fp16 weights.
// Softmax over w (rows) per (batch, v column). block (32,16), grid (32, nb).
// ---------------------------------------------------------------------------
__global__ __launch_bounds__(512) void softmax_col(half* __restrict__ att)
{
    __shared__ float red[16][33];
    const int tx = threadIdx.x, ty = threadIdx.y;
    const size_t base = (size_t)blockIdx.y * VDIM * VDIM + (size_t)blockIdx.x * 32 + tx;

    float vals[64];
    float m = -INFINITY;
#pragma unroll
    for (int k = 0; k < 64; k++) {
        vals[k] = __half2float(att[base + (size_t)(ty + 16 * k) * VDIM]);
        m = fmaxf(m, vals[k]);
    }
    red[ty][tx] = m;
    __syncthreads();
#pragma unroll
    for (int off = 8; off >= 1; off >>= 1) {
        if (ty < off) red[ty][tx] = fmaxf(red[ty][tx], red[ty + off][tx]);
        __syncthreads();
    }
    m = red[0][tx];
    __syncthreads();

    float s = 0.f;
#pragma unroll
    for (int k = 0; k < 64; k++) {
        vals[k] = __expf(vals[k] - m);
        s += vals[k];
    }
    red[ty][tx] = s;
    __syncthreads();
#pragma unroll
    for (int off = 8; off >= 1; off >>= 1) {
        if (ty < off) red[ty][tx] += red[ty + off][tx];
        __syncthreads();
    }
    const float inv = 1.0f / red[0][tx];

#pragma unroll
    for (int k = 0; k < 64; k++) {
        const size_t idx = base + (size_t)(ty + 16 * k) * VDIM;
        att[idx] = __float2half_rn(vals[k] * inv);
    }
}

// ---------------------------------------------------------------------------
extern "C" void kernel_launch(void* const* d_in, const int* in_sizes, int n_in,
                              void* d_out, int out_size)
{
    const float* input = (const float*)d_in[0];
    const float* Wq    = (const float*)d_in[1];
    const float* bq    = (const float*)d_in[2];
    const float* Wk    = (const float*)d_in[3];
    const float* bk    = (const float*)d_in[4];
    const float* Wv    = (const float*)d_in[5];
    const float* bv    = (const float*)d_in[6];
    const float* gamma = (const float*)d_in[7];
    float* out = (float*)d_out;

    half *in_f16, *wq_f16, *wk_f16, *wv_f16, *qT, *kT, *v_f16, *att_f16;
    cudaGetSymbolAddress((void**)&in_f16, g_in_f16);
    cudaGetSymbolAddress((void**)&wq_f16, g_wq_f16);
    cudaGetSymbolAddress((void**)&wk_f16, g_wk_f16);
    cudaGetSymbolAddress((void**)&wv_f16, g_wv_f16);
    cudaGetSymbolAddress((void**)&qT, g_qT);
    cudaGetSymbolAddress((void**)&kT, g_kT);
    cudaGetSymbolAddress((void**)&v_f16, g_v_f16);
    cudaGetSymbolAddress((void**)&att_f16, g_att_f16);

    cudaFuncSetAttribute(gemm_f16<0>, cudaFuncAttributeMaxDynamicSharedMemorySize, SMEM_F16);
    cudaFuncSetAttribute(gemm_f16<1>, cudaFuncAttributeMaxDynamicSharedMemorySize, SMEM_F16);
    cudaFuncSetAttribute(gemm_f16<2>, cudaFuncAttributeMaxDynamicSharedMemorySize, SMEM_F16);
    cudaFuncSetAttribute(gemm_f16<3>, cudaFuncAttributeMaxDynamicSharedMemorySize, SMEM_F16);

    // Streams (created once, outside capture): sv = v branch, ss = batch-half
    // pipeline of attn/softmax.
    static cudaStream_t sv = nullptr, ss = nullptr;
    static cudaEvent_t evFork = nullptr, evJoin = nullptr, evSlab = nullptr;
    static cudaEvent_t evQK = nullptr, evS1 = nullptr;
    if (sv == nullptr) {
        cudaStreamCreateWithFlags(&sv, cudaStreamNonBlocking);
        cudaStreamCreateWithFlags(&ss, cudaStreamNonBlocking);
        cudaEventCreateWithFlags(&evFork, cudaEventDisableTiming);
        cudaEventCreateWithFlags(&evJoin, cudaEventDisableTiming);
        cudaEventCreateWithFlags(&evSlab, cudaEventDisableTiming);
        cudaEventCreateWithFlags(&evQK, cudaEventDisableTiming);
        cudaEventCreateWithFlags(&evS1, cudaEventDisableTiming);
    }

    const long long MN = (long long)BATCH * SEQ;   // 32768
    const long long BSEQ = (long long)SEQ * VDIM;  // 4194304
    const long long AT = (long long)VDIM * VDIM;   // 1048576
    const int HB = BATCH / 2;                      // 4 batches per half

    // Fork side stream at entry.
    cudaEventRecord(evFork, 0);
    cudaStreamWaitEvent(sv, evFork, 0);

    // Main stream: convert ONLY the KQ slab (cols 768..1023) of input.
    convert_f16_slab<<<512, 256>>>(input, in_f16, VDIM - KQDIM, KQDIM, (size_t)MN);
    cudaEventRecord(evSlab, 0);

    // Side stream sv: Wv + remaining input columns, then v GEMM.
    convert_f16<<<256, 256, 0, sv>>>(Wv, wv_f16, (size_t)VDIM * VDIM / 4);
    convert_f16_slab<<<1536, 256, 0, sv>>>(input, in_f16, 0, VDIM - KQDIM, (size_t)MN);
    cudaStreamWaitEvent(sv, evSlab, 0);
    gemm_f16<2><<<dim3(8, 256, 1), 256, SMEM_F16, sv>>>(
        in_f16, VDIM, 0, wv_f16, VDIM, 0,
        nullptr, v_f16, VDIM, 0, bv, nullptr, nullptr,
        nullptr, nullptr, nullptr, VDIM / 64);
    cudaEventRecord(evJoin, sv);

    // Main branch: weight converts, merged q/k.
    convert_f16<<<64, 256>>>(Wq, wq_f16, (size_t)VDIM * KQDIM / 4);
    convert_f16<<<64, 256>>>(Wk, wk_f16, (size_t)VDIM * KQDIM / 4);

    gemm_f16<1><<<dim3(256, 8, 2), 256, SMEM_F16>>>(
        wq_f16, KQDIM, 0,
        in_f16 + (VDIM - KQDIM), VDIM, 0,
        nullptr, qT, MN, 0, bq, nullptr, nullptr,
        wk_f16, bk, kT, KQDIM / 64);
    cudaEventRecord(evQK, 0);

    // Batch-half pipeline:
    //   main: attn[0..3] -> softmax[0..3] -> (wait v) out[0..3] -> (wait evS1) out[4..7]
    //   ss:   (wait evQK) attn[4..7] -> softmax[4..7] -> evS1
    // The two 256-CTA attn grids run concurrently (same machine fill as one
    // 512-CTA grid); each half's softmax overlaps the other half's work.
    gemm_f16<0><<<dim3(8, 8, HB), 256, SMEM_F16>>>(
        qT, MN, SEQ, kT, MN, SEQ,
        nullptr, att_f16, VDIM, AT, nullptr, nullptr, nullptr,
        nullptr, nullptr, nullptr, SEQ / 64);

    cudaStreamWaitEvent(ss, evQK, 0);
    gemm_f16<0><<<dim3(8, 8, HB), 256, SMEM_F16, ss>>>(
        qT + (size_t)HB * SEQ, MN, SEQ, kT + (size_t)HB * SEQ, MN, SEQ,
        nullptr, att_f16 + (size_t)HB * AT, VDIM, AT, nullptr, nullptr, nullptr,
        nullptr, nullptr, nullptr, SEQ / 64);

    softmax_col<<<dim3(VDIM / 32, HB), dim3(32, 16)>>>(att_f16);
    softmax_col<<<dim3(VDIM / 32, HB), dim3(32, 16), 0, ss>>>(
        att_f16 + (size_t)HB * AT);
    cudaEventRecord(evS1, ss);

    // out[0..3]: needs v + softmax[0..3]
    cudaStreamWaitEvent(0, evJoin, 0);
    gemm_f16<3><<<dim3(8, 32, HB), 256, SMEM_F16>>>(
        v_f16, VDIM, BSEQ, att_f16, VDIM, AT,
        out, nullptr, VDIM, BSEQ, nullptr, input, gamma,
        nullptr, nullptr, nullptr, VDIM / 64);
    // out[4..7]: additionally needs softmax[4..7]
    cudaStreamWaitEvent(0, evS1, 0);
    gemm_f16<3><<<dim3(8, 32, HB), 256, SMEM_F16>>>(
        v_f16 + (size_t)HB * BSEQ, VDIM, BSEQ, att_f16 + (size_t)HB * AT, VDIM, AT,
        out + (size_t)HB * BSEQ, nullptr, VDIM, BSEQ, nullptr,
        input + (size_t)HB * BSEQ, gamma,
        nullptr, nullptr, nullptr, VDIM / 64);
}